// round 16
// baseline (speedup 1.0000x reference)
#include <cuda_runtime.h>
#include <cuda_fp16.h>
#include <math.h>
#include <stdint.h>

// Problem sizes
constexpr int SS  = 128;    // S
constexpr int BB  = 32;     // B
constexpr int TT  = 64;     // T
constexpr int HH  = 512;    // H
constexpr int HH2 = 1024;   // 2H
constexpr int VV  = 32000;  // V
constexpr int GG  = 2048;   // 4H
constexpr int KK  = 1536;   // 3H (concat K for logits GEMM)
constexpr int KSP = 8;      // k-split factor (ct part of gates; sv)
constexpr int KSH = 2;      // k-split factor for s@W_hh^T part

// logits fp16-mma tiling (R7 config: LN=256, 8 warps, NSTG=4)
constexpr int LN   = 256;         // n per block
constexpr int LTH  = 256;         // threads (8 warps)
constexpr int LKC  = 32;          // k per chunk
constexpr int KP   = LKC / 2;     // 16 half2 rows per chunk
constexpr int NCH  = KK / LKC;    // 48 chunks
constexpr int NSTG = 4;           // pipeline stages
constexpr int WST  = 264;         // W smem row stride (b32)
constexpr int XST  = 20;          // X smem row stride (b32)
constexpr int WBUF = KP * WST;    // 4224 b32
constexpr int XBUF = BB * XST;    // 640 b32
constexpr int LSMEM_BYTES = NSTG * (WBUF + XBUF) * 4;  // 77824

// ---------------- device scratch (static, allocation-free) ----------------
__device__ float g_wa_h[SS * BB * HH];        // 8 MB: precomputed h_s @ w_a
__device__ float g_svp[KSP][BB][HH];          // sv partials
__device__ float g_sv[BB][HH];                // s @ v_a
__device__ float g_scores[SS * BB];
__device__ float g_ct[BB][HH2];
__device__ float g_gatesp[KSP][BB][GG];       // gates partials (ct part, K=1024)
__device__ float g_gatesph[KSH][BB][GG];      // gates partials (s part, K=512)
__device__ float g_s[BB][HH];
__device__ float g_c[BB][HH];
__device__ __align__(16) __half g_xh[TT][BB][KK];  // per-step concat [s|ct] fp16 (6.3MB)
__device__ __half2 g_wh[(size_t)(KK / 2) * VV];    // 98.3 MB fp16 weights
__device__ float g_logits[BB][VV];            // 4 MB
__device__ float g_nll[BB];

__device__ __forceinline__ float sigf(float x) { return 1.f / (1.f + expf(-x)); }

__device__ __forceinline__ void cpa16(uint32_t dst, const void* src) {
  asm volatile("cp.async.cg.shared.global [%0], [%1], 16;\n" ::"r"(dst), "l"(src));
}

__device__ __forceinline__ void mma_f16(float* d, const uint32_t* a, uint32_t b0,
                                        uint32_t b1) {
  asm volatile(
      "mma.sync.aligned.m16n8k16.row.col.f32.f16.f16.f32 "
      "{%0,%1,%2,%3}, {%4,%5,%6,%7}, {%8,%9}, {%0,%1,%2,%3};\n"
      : "+f"(d[0]), "+f"(d[1]), "+f"(d[2]), "+f"(d[3])
      : "r"(a[0]), "r"(a[1]), "r"(a[2]), "r"(a[3]), "r"(b0), "r"(b1));
}

// ---------------- init ----------------
__global__ void k_init() {
  int b = blockIdx.x, h = threadIdx.x;
  g_s[b][h] = 0.f;
  g_c[b][h] = 0.f;
  if (b == 0 && h < BB) g_nll[h] = 0.f;
}

// ---------------- weight conversion: fp32 [w_b;v_b] -> fp16 pair-interleaved ----
__global__ void k_conv(const float* __restrict__ w_b, const float* __restrict__ v_b) {
  int n = blockIdx.x * 256 + threadIdx.x;
  int kp = blockIdx.y;
  int k0 = 2 * kp;
  const float* r0 = (k0 < HH) ? w_b + (size_t)k0 * VV : v_b + (size_t)(k0 - HH) * VV;
  const float* r1 =
      (k0 + 1 < HH) ? w_b + (size_t)(k0 + 1) * VV : v_b + (size_t)(k0 + 1 - HH) * VV;
  g_wh[(size_t)kp * VV + n] = __floats2half2_rn(r0[n], r1[n]);
}

// ---------------- wa_h = h_s @ w_a : [4096,1024]x[1024,512] (one-time) --------
__global__ __launch_bounds__(256) void k_wa_h(const float* __restrict__ h_s,
                                              const float* __restrict__ w_a) {
  __shared__ float As[32][64];  // [k][r]
  __shared__ float Ws[32][64];  // [k][j]
  int rb = blockIdx.x * 64;
  int jb = blockIdx.y * 64;
  int tid = threadIdx.x;
  int tx = tid & 15, ty = tid >> 4;
  float acc[4][4] = {};
  for (int k0 = 0; k0 < HH2; k0 += 32) {
    {
      int r = tid >> 2;
      int kk = (tid & 3) * 8;
      const float4* asrc =
          reinterpret_cast<const float4*>(h_s + (size_t)(rb + r) * HH2 + k0 + kk);
      float4 a0 = asrc[0], a1 = asrc[1];
      As[kk + 0][r] = a0.x; As[kk + 1][r] = a0.y; As[kk + 2][r] = a0.z; As[kk + 3][r] = a0.w;
      As[kk + 4][r] = a1.x; As[kk + 5][r] = a1.y; As[kk + 6][r] = a1.z; As[kk + 7][r] = a1.w;
    }
    {
      int kw = tid >> 3;
      int j = (tid & 7) * 8;
      const float4* wsrc =
          reinterpret_cast<const float4*>(w_a + (size_t)(k0 + kw) * HH + jb + j);
      *reinterpret_cast<float4*>(&Ws[kw][j])     = wsrc[0];
      *reinterpret_cast<float4*>(&Ws[kw][j + 4]) = wsrc[1];
    }
    __syncthreads();
#pragma unroll
    for (int k = 0; k < 32; k++) {
      float4 a = *reinterpret_cast<float4*>(&As[k][ty * 4]);
      float4 w = *reinterpret_cast<float4*>(&Ws[k][tx * 4]);
      acc[0][0] += a.x * w.x; acc[0][1] += a.x * w.y; acc[0][2] += a.x * w.z; acc[0][3] += a.x * w.w;
      acc[1][0] += a.y * w.x; acc[1][1] += a.y * w.y; acc[1][2] += a.y * w.z; acc[1][3] += a.y * w.w;
      acc[2][0] += a.z * w.x; acc[2][1] += a.z * w.y; acc[2][2] += a.z * w.z; acc[2][3] += a.z * w.w;
      acc[3][0] += a.w * w.x; acc[3][1] += a.w * w.y; acc[3][2] += a.w * w.z; acc[3][3] += a.w * w.w;
    }
    __syncthreads();
  }
#pragma unroll
  for (int ii = 0; ii < 4; ii++)
#pragma unroll
    for (int jj = 0; jj < 4; jj++)
      g_wa_h[(size_t)(rb + ty * 4 + ii) * HH + jb + tx * 4 + jj] = acc[ii][jj];
}

// ---------------- fused s-dependent GEMMs: sv partials + gates_h partials ----
// grid = 128 blocks: [0,64) sv tiles (8j x 8ksplit); [64,128) s@W_hh^T tiles
// (32j x 2ksplit). Both depend only on g_s; identical per-block parallelism to
// the standalone kernels, launched as ONE graph node.
__global__ __launch_bounds__(256) void k_svgh(const float* __restrict__ v_a,
                                              const float* __restrict__ W_hh) {
  __shared__ float Ws[64][64];  // [k][j]
  __shared__ float Xs[64][33];  // [k][b]
  const int bid = blockIdx.x;
  const int tid = threadIdx.x;
  const int tx = tid & 15, ty = tid >> 4;  // j0=tx*4, b0=ty*2

  if (bid < 64) {
    // ---- sv: s @ v_a ----
    int jb = (bid & 7) * 64;
    int k0 = (bid >> 3) * 64;
    {
      int k = tid >> 2;
      int jq = (tid & 3) * 16;
      const float* src = v_a + (size_t)(k0 + k) * HH + jb + jq;
#pragma unroll
      for (int c = 0; c < 4; c++)
        *reinterpret_cast<float4*>(&Ws[k][jq + c * 4]) =
            *reinterpret_cast<const float4*>(src + c * 4);
    }
    {
      int b = tid >> 3;
      int k8 = (tid & 7) * 8;
      const float* src = &g_s[b][k0 + k8];
      float4 x0 = *reinterpret_cast<const float4*>(src);
      float4 x1 = *reinterpret_cast<const float4*>(src + 4);
      Xs[k8 + 0][b] = x0.x; Xs[k8 + 1][b] = x0.y; Xs[k8 + 2][b] = x0.z; Xs[k8 + 3][b] = x0.w;
      Xs[k8 + 4][b] = x1.x; Xs[k8 + 5][b] = x1.y; Xs[k8 + 6][b] = x1.z; Xs[k8 + 7][b] = x1.w;
    }
    __syncthreads();
    float acc[2][4] = {};
#pragma unroll
    for (int k = 0; k < 64; k++) {
      float4 w = *reinterpret_cast<float4*>(&Ws[k][tx * 4]);
      float x0 = Xs[k][ty * 2], x1 = Xs[k][ty * 2 + 1];
      acc[0][0] += x0 * w.x; acc[0][1] += x0 * w.y; acc[0][2] += x0 * w.z; acc[0][3] += x0 * w.w;
      acc[1][0] += x1 * w.x; acc[1][1] += x1 * w.y; acc[1][2] += x1 * w.z; acc[1][3] += x1 * w.w;
    }
#pragma unroll
    for (int bi = 0; bi < 2; bi++)
#pragma unroll
      for (int ji = 0; ji < 4; ji++)
        g_svp[bid >> 3][ty * 2 + bi][jb + (bid & 7) * 0 + ((bid & 7) * 64) * 0 + jb * 0 +
                                     tx * 4 + ji] = acc[bi][ji];  // note: jb used below
    // (the line above writes g_svp[kt][b][jb + tx*4+ji]; expression kept simple:)
  } else {
    // ---- gates_h: s @ W_hh^T partials ----
    int gid = bid - 64;
    int jb = (gid & 31) * 64;   // j over GG=2048
    int kh = gid >> 5;          // 0..1
    float acc[2][4] = {};
    for (int kt = 0; kt < 4; kt++) {
      int k0 = kh * 256 + kt * 64;  // k within HH=512
      {
        int jl = tid >> 2;
        int kq = (tid & 3) * 16;
#pragma unroll
        for (int c = 0; c < 4; c++) {
          int kg = k0 + kq + c * 4;
          float4 w = *reinterpret_cast<const float4*>(W_hh + (size_t)(jb + jl) * HH + kg);
          int kl = kq + c * 4;
          Ws[kl + 0][jl] = w.x; Ws[kl + 1][jl] = w.y; Ws[kl + 2][jl] = w.z; Ws[kl + 3][jl] = w.w;
        }
      }
      {
        int bq = tid >> 3;
        int k8 = (tid & 7) * 8;
#pragma unroll
        for (int c = 0; c < 8; c++) Xs[k8 + c][bq] = g_s[bq][k0 + k8 + c];
      }
      __syncthreads();
#pragma unroll
      for (int k = 0; k < 64; k++) {
        float4 w = *reinterpret_cast<float4*>(&Ws[k][tx * 4]);
        float x0 = Xs[k][ty * 2], x1 = Xs[k][ty * 2 + 1];
        acc[0][0] += x0 * w.x; acc[0][1] += x0 * w.y; acc[0][2] += x0 * w.z; acc[0][3] += x0 * w.w;
        acc[1][0] += x1 * w.x; acc[1][1] += x1 * w.y; acc[1][2] += x1 * w.z; acc[1][3] += x1 * w.w;
      }
      __syncthreads();
    }
#pragma unroll
    for (int bi = 0; bi < 2; bi++)
#pragma unroll
      for (int ji = 0; ji < 4; ji++)
        g_gatesph[kh][ty * 2 + bi][jb + tx * 4 + ji] = acc[bi][ji];
  }
}

__global__ void k_svred() {
  int b = blockIdx.x, h = threadIdx.x;
  float s = 0.f;
#pragma unroll
  for (int ks = 0; ks < KSP; ks++) s += g_svp[ks][b][h];
  g_sv[b][h] = s;
}

// ---------------- scores[i,b] = (u_a . tanh(wa_h + sv)) * mask ----------------
__global__ __launch_bounds__(128) void k_scores(const float* __restrict__ u_a,
                                                const float* __restrict__ s_mask) {
  int i = blockIdx.x, b = blockIdx.y;
  int tid = threadIdx.x;
  const float* wah = g_wa_h + (size_t)(i * BB + b) * HH;
  float part = 0.f;
#pragma unroll
  for (int c = 0; c < 4; c++) {
    int h = tid + c * 128;
    float x = wah[h] + g_sv[b][h];
    float th;
    asm("tanh.approx.f32 %0, %1;" : "=f"(th) : "f"(x));
    part += u_a[h] * th;
  }
#pragma unroll
  for (int o = 16; o > 0; o >>= 1) part += __shfl_xor_sync(0xffffffffu, part, o);
  __shared__ float red[4];
  if ((tid & 31) == 0) red[tid >> 5] = part;
  __syncthreads();
  if (tid == 0)
    g_scores[i * BB + b] = (red[0] + red[1] + red[2] + red[3]) * s_mask[i * BB + b];
}

// ---------------- ct: inline softmax over S, then weighted sum ----------------
__global__ __launch_bounds__(128) void k_ct(const float* __restrict__ h_s, int t) {
  int b = blockIdx.x;
  int tid = threadIdx.x;  // 128 == SS
  __shared__ float al[SS];
  __shared__ float red[4];
  __shared__ float bc[2];
  float sc = g_scores[tid * BB + b];
  float m = sc;
#pragma unroll
  for (int o = 16; o > 0; o >>= 1) m = fmaxf(m, __shfl_xor_sync(0xffffffffu, m, o));
  if ((tid & 31) == 0) red[tid >> 5] = m;
  __syncthreads();
  if (tid == 0) bc[0] = fmaxf(fmaxf(red[0], red[1]), fmaxf(red[2], red[3]));
  __syncthreads();
  float e = __expf(sc - bc[0]);
  float s = e;
#pragma unroll
  for (int o = 16; o > 0; o >>= 1) s += __shfl_xor_sync(0xffffffffu, s, o);
  __syncthreads();
  if ((tid & 31) == 0) red[tid >> 5] = s;
  __syncthreads();
  if (tid == 0) bc[1] = red[0] + red[1] + red[2] + red[3];
  __syncthreads();
  al[tid] = e / bc[1];
  __syncthreads();
  int d = blockIdx.y * 128 + tid;
  float acc = 0.f;
  const float* base = h_s + (size_t)b * HH2 + d;
#pragma unroll 4
  for (int i = 0; i < SS; i++) acc += al[i] * base[(size_t)i * BB * HH2];
  g_ct[b][d] = acc;
  g_xh[t][b][HH + d] = __float2half(acc);
}

// ---------------- gates partials (ct part only): ct @ W_ih[:,0:1024]^T --------
__global__ __launch_bounds__(256) void k_gates(const float* __restrict__ W_ih) {
  __shared__ float Ws[64][64];  // [k][j]
  __shared__ float Xs[64][33];  // [k][b]
  int jb = blockIdx.x * 64;
  int ks = blockIdx.y;          // 8 splits x 128 k
  int tid = threadIdx.x;
  int tx = tid & 15, ty = tid >> 4;
  float acc[2][4] = {};
  for (int kt = 0; kt < 2; kt++) {
    int k0 = ks * 128 + kt * 64;
    {
      int jl = tid >> 2;
      int kq = (tid & 3) * 16;
#pragma unroll
      for (int c = 0; c < 4; c++) {
        int kg = k0 + kq + c * 4;
        float4 w = *reinterpret_cast<const float4*>(W_ih + (size_t)(jb + jl) * HH2 + kg);
        int kl = kq + c * 4;
        Ws[kl + 0][jl] = w.x; Ws[kl + 1][jl] = w.y; Ws[kl + 2][jl] = w.z; Ws[kl + 3][jl] = w.w;
      }
    }
    {
      int bq = tid >> 3;
      int k8 = (tid & 7) * 8;
#pragma unroll
      for (int c = 0; c < 8; c++) Xs[k8 + c][bq] = g_ct[bq][k0 + k8 + c];
    }
    __syncthreads();
#pragma unroll
    for (int k = 0; k < 64; k++) {
      float4 w = *reinterpret_cast<float4*>(&Ws[k][tx * 4]);
      float x0 = Xs[k][ty * 2], x1 = Xs[k][ty * 2 + 1];
      acc[0][0] += x0 * w.x; acc[0][1] += x0 * w.y; acc[0][2] += x0 * w.z; acc[0][3] += x0 * w.w;
      acc[1][0] += x1 * w.x; acc[1][1] += x1 * w.y; acc[1][2] += x1 * w.z; acc[1][3] += x1 * w.w;
    }
    __syncthreads();
  }
#pragma unroll
  for (int bi = 0; bi < 2; bi++)
#pragma unroll
    for (int ji = 0; ji < 4; ji++)
      g_gatesp[blockIdx.y][ty * 2 + bi][jb + tx * 4 + ji] = acc[bi][ji];
}

// ---------------- LSTM cell pointwise ----------------
__global__ __launch_bounds__(512) void k_lstm(const float* __restrict__ b_ih,
                                              const float* __restrict__ b_hh, int t) {
  int b = blockIdx.x, h = threadIdx.x;
  float gi = b_ih[h] + b_hh[h];
  float gf = b_ih[HH + h] + b_hh[HH + h];
  float gg = b_ih[2 * HH + h] + b_hh[2 * HH + h];
  float go = b_ih[3 * HH + h] + b_hh[3 * HH + h];
#pragma unroll
  for (int ks = 0; ks < KSP; ks++) {
    gi += g_gatesp[ks][b][h];
    gf += g_gatesp[ks][b][HH + h];
    gg += g_gatesp[ks][b][2 * HH + h];
    go += g_gatesp[ks][b][3 * HH + h];
  }
#pragma unroll
  for (int kh = 0; kh < KSH; kh++) {
    gi += g_gatesph[kh][b][h];
    gf += g_gatesph[kh][b][HH + h];
    gg += g_gatesph[kh][b][2 * HH + h];
    go += g_gatesph[kh][b][3 * HH + h];
  }
  float c = g_c[b][h];
  float cn = sigf(gf) * c + sigf(gi) * tanhf(gg);
  float sn = sigf(go) * tanhf(cn);
  g_c[b][h] = cn;
  g_s[b][h] = sn;
  g_xh[t][b][h] = __float2half(sn);
}

// ---------------- logits via fp16 mma (R7 config) ----------------
__global__ __launch_bounds__(LTH, 1) void k_logits_mma(int t) {
  extern __shared__ uint32_t smw[];
  const int nb = blockIdx.x * LN;
  const int tid = threadIdx.x;
  const int warp = tid >> 5, lane = tid & 31;
  const int grp = lane >> 2, tig = lane & 3;

  uint32_t sbase = (uint32_t)__cvta_generic_to_shared(smw);
  const uint32_t xbase = sbase + NSTG * WBUF * 4;

  const int wr0 = tid >> 6;
  const int wn4 = (tid & 63) * 4;
  const int xrow = tid >> 2;
  const int xo = tid & 3;

  float acc[2][4][4];
#pragma unroll
  for (int i = 0; i < 2; i++)
#pragma unroll
    for (int j = 0; j < 4; j++)
#pragma unroll
      for (int k = 0; k < 4; k++) acc[i][j][k] = 0.f;

#define STAGE(buf, kp0)                                                            \
  do {                                                                             \
    _Pragma("unroll") for (int kk = 0; kk < 4; kk++) {                             \
      int r = wr0 + kk * 4;                                                        \
      cpa16(sbase + ((buf)*WBUF + r * WST + wn4) * 4,                              \
            g_wh + (size_t)((kp0) + r) * VV + nb + wn4);                           \
    }                                                                              \
    if (tid < 128)                                                                 \
      cpa16(xbase + ((buf)*XBUF + xrow * XST + xo * 4) * 4,                        \
            &g_xh[t][xrow][(kp0)*2 + xo * 8]);                                     \
  } while (0)

#pragma unroll
  for (int p = 0; p < NSTG - 1; p++) {
    STAGE(p, p * KP);
    asm volatile("cp.async.commit_group;\n");
  }

  for (int c = 0; c < NCH; c++) {
    int buf = c & (NSTG - 1);
    asm volatile("cp.async.wait_group %0;\n" ::"n"(NSTG - 2));
    __syncthreads();

    if (c + NSTG - 1 < NCH) STAGE((c + NSTG - 1) & (NSTG - 1), (c + NSTG - 1) * KP);
    asm volatile("cp.async.commit_group;\n");

    const uint32_t* Wc = smw + buf * WBUF;
    const uint32_t* Xc = smw + NSTG * WBUF + buf * XBUF;
#pragma unroll
    for (int ks2 = 0; ks2 < KP; ks2 += 8) {
      uint32_t A[2][4];
#pragma unroll
      for (int mt = 0; mt < 2; mt++) {
        int r0 = mt * 16 + grp;
        A[mt][0] = Xc[r0 * XST + ks2 + tig];
        A[mt][1] = Xc[(r0 + 8) * XST + ks2 + tig];
        A[mt][2] = Xc[r0 * XST + ks2 + 4 + tig];
        A[mt][3] = Xc[(r0 + 8) * XST + ks2 + 4 + tig];
      }
#pragma unroll
      for (int nt = 0; nt < 4; nt++) {
        int n0 = warp * 32 + nt * 8 + grp;
        uint32_t B0 = Wc[(ks2 + tig) * WST + n0];
        uint32_t B1 = Wc[(ks2 + 4 + tig) * WST + n0];
        mma_f16(acc[0][nt], A[0], B0, B1);
        mma_f16(acc[1][nt], A[1], B0, B1);
      }
    }
  }
#undef STAGE

#pragma unroll
  for (int mt = 0; mt < 2; mt++) {
#pragma unroll
    for (int nt = 0; nt < 4; nt++) {
      int row = mt * 16 + grp;
      int col = nb + warp * 32 + nt * 8 + tig * 2;
      float2 lo = {acc[mt][nt][0], acc[mt][nt][1]};
      float2 hi = {acc[mt][nt][2], acc[mt][nt][3]};
      *reinterpret_cast<float2*>(&g_logits[row][col]) = lo;
      *reinterpret_cast<float2*>(&g_logits[row + 8][col]) = hi;
    }
  }
}

// ---------------- softmax over V, write p_gen, accumulate NLL ----------------
__global__ __launch_bounds__(512) void k_softmax(float* __restrict__ out,
                                                 const int* __restrict__ t_indices,
                                                 const float* __restrict__ t_mask,
                                                 int t, long long p_off) {
  int b = blockIdx.x, tid = threadIdx.x;
  const float* lg = g_logits[b];
  __shared__ float red[16];
  __shared__ float bc[2];
  float m = -3.4e38f;
  for (int v = tid; v < VV; v += 512) m = fmaxf(m, lg[v]);
#pragma unroll
  for (int o = 16; o > 0; o >>= 1) m = fmaxf(m, __shfl_xor_sync(0xffffffffu, m, o));
  if ((tid & 31) == 0) red[tid >> 5] = m;
  __syncthreads();
  if (tid == 0) {
    float mm = red[0];
#pragma unroll
    for (int w = 1; w < 16; w++) mm = fmaxf(mm, red[w]);
    bc[0] = mm;
  }
  __syncthreads();
  m = bc[0];
  float s = 0.f;
  for (int v = tid; v < VV; v += 512) s += __expf(lg[v] - m);
#pragma unroll
  for (int o = 16; o > 0; o >>= 1) s += __shfl_xor_sync(0xffffffffu, s, o);
  __syncthreads();
  if ((tid & 31) == 0) red[tid >> 5] = s;
  __syncthreads();
  if (tid == 0) {
    float ss = 0.f;
#pragma unroll
    for (int w = 0; w < 16; w++) ss += red[w];
    bc[1] = ss;
  }
  __syncthreads();
  float Z = bc[1];
  float inv = 1.f / Z;
  float* dst = out + p_off + ((long long)t * BB + b) * VV;
  for (int v = tid; v < VV; v += 512) dst[v] = __expf(lg[v] - m) * inv;
  if (tid == 0) {
    int idx = t_indices[t * BB + b];
    g_nll[b] += -(lg[idx] - m - logf(Z)) * t_mask[t * BB + b];
  }
}

// ---------------- final loss ----------------
__global__ void k_loss(float* __restrict__ out, const float* __restrict__ t_mask) {
  int b = threadIdx.x;  // 32
  float s = 0.f;
  for (int t = 0; t < TT; t++) s += t_mask[t * BB + b];
  out[b] = g_nll[b] / s;
}

// ---------------- launch: dual-stream pipelined graph ----------------
extern "C" void kernel_launch(void* const* d_in, const int* in_sizes, int n_in,
                              void* d_out, int out_size) {
  const float* h_s    = (const float*)d_in[0];
  const float* s_mask = (const float*)d_in[1];
  const float* w_a    = (const float*)d_in[2];
  const float* v_a    = (const float*)d_in[3];
  const float* u_a    = (const float*)d_in[4];
  const float* w_b    = (const float*)d_in[5];
  const float* v_b    = (const float*)d_in[6];
  const float* W_ih   = (const float*)d_in[7];
  const float* W_hh   = (const float*)d_in[8];
  const float* b_ih   = (const float*)d_in[9];
  const float* b_hh   = (const float*)d_in[10];
  const float* t_mask = (const float*)d_in[11];
  const int*   t_idx  = (const int*)d_in[12];
  float* out = (float*)d_out;

  long long p_off = (long long)out_size - (long long)TT * BB * VV;
  if (p_off < 0) p_off = 0;

  static cudaStream_t sA = nullptr, sB = nullptr;
  static cudaEvent_t evFork, evA[TT], evLastA, evLastB;
  if (sA == nullptr) {
    cudaStreamCreateWithFlags(&sA, cudaStreamNonBlocking);
    cudaStreamCreateWithFlags(&sB, cudaStreamNonBlocking);
    cudaEventCreateWithFlags(&evFork, cudaEventDisableTiming);
    cudaEventCreateWithFlags(&evLastA, cudaEventDisableTiming);
    cudaEventCreateWithFlags(&evLastB, cudaEventDisableTiming);
    for (int t = 0; t < TT; t++)
      cudaEventCreateWithFlags(&evA[t], cudaEventDisableTiming);
    cudaFuncSetAttribute(k_logits_mma, cudaFuncAttributeMaxDynamicSharedMemorySize,
                         LSMEM_BYTES);
  }

  // prologue on origin (default) stream
  k_init<<<BB, HH>>>();
  k_conv<<<dim3(VV / 256, KK / 2), 256>>>(w_b, v_b);
  k_wa_h<<<dim3(64, 8), 256>>>(h_s, w_a);

  // fork capture into sA (recurrence) and sB (output head)
  cudaEventRecord(evFork, 0);
  cudaStreamWaitEvent(sA, evFork, 0);
  cudaStreamWaitEvent(sB, evFork, 0);

  for (int t = 0; t < TT; t++) {
    k_svgh<<<128, 256, 0, sA>>>(v_a, W_hh);
    k_svred<<<BB, HH, 0, sA>>>();
    k_scores<<<dim3(SS, BB), 128, 0, sA>>>(u_a, s_mask);
    k_ct<<<dim3(BB, 8), 128, 0, sA>>>(h_s, t);
    k_gates<<<dim3(32, KSP), 256, 0, sA>>>(W_ih);
    k_lstm<<<BB, HH, 0, sA>>>(b_ih, b_hh, t);
    cudaEventRecord(evA[t], sA);

    cudaStreamWaitEvent(sB, evA[t], 0);
    k_logits_mma<<<VV / LN, LTH, LSMEM_BYTES, sB>>>(t);
    k_softmax<<<BB, 512, 0, sB>>>(out, t_idx, t_mask, t, p_off);
  }

  // join both branches back into origin stream before k_loss
  cudaEventRecord(evLastA, sA);
  cudaEventRecord(evLastB, sB);
  cudaStreamWaitEvent((cudaStream_t)0, evLastA, 0);
  cudaStreamWaitEvent((cudaStream_t)0, evLastB, 0);
  k_loss<<<1, BB>>>(out, t_mask);
}

// round 17
// speedup vs baseline: 1.1036x; 1.1036x over previous
#include <cuda_runtime.h>
#include <cuda_fp16.h>
#include <math.h>
#include <stdint.h>

// Problem sizes
constexpr int SS  = 128;    // S
constexpr int BB  = 32;     // B
constexpr int TT  = 64;     // T
constexpr int HH  = 512;    // H
constexpr int HH2 = 1024;   // 2H
constexpr int VV  = 32000;  // V
constexpr int GG  = 2048;   // 4H
constexpr int KK  = 1536;   // 3H (concat K for logits GEMM)
constexpr int KSP = 8;      // k-split factor for small GEMMs

// logits fp16-mma tiling (R7 config: LN=256, 8 warps, NSTG=4)
constexpr int LN   = 256;         // n per block
constexpr int LTH  = 256;         // threads (8 warps)
constexpr int LKC  = 32;          // k per chunk
constexpr int KP   = LKC / 2;     // 16 half2 rows per chunk
constexpr int NCH  = KK / LKC;    // 48 chunks
constexpr int NSTG = 4;           // pipeline stages
constexpr int WST  = 264;         // W smem row stride (b32)
constexpr int XST  = 20;          // X smem row stride (b32)
constexpr int WBUF = KP * WST;    // 4224 b32
constexpr int XBUF = BB * XST;    // 640 b32
constexpr int LSMEM_BYTES = NSTG * (WBUF + XBUF) * 4;  // 77824

// ---------------- device scratch (static, allocation-free) ----------------
__device__ float g_wa_h[SS * BB * HH];        // 8 MB: precomputed h_s @ w_a
__device__ float g_svp[KSP][BB][HH];          // sv partials
__device__ float g_sv[BB][HH];                // s @ v_a
__device__ float g_scores[SS * BB];
__device__ float g_ct[BB][HH2];
__device__ float g_gatesp[KSP][BB][GG];       // gates partials
__device__ float g_s[BB][HH];
__device__ float g_c[BB][HH];
__device__ __align__(16) __half g_xh[TT][BB][KK];  // per-step concat [s|ct] (6.3MB)
__device__ __half2 g_wh[(size_t)(KK / 2) * VV];    // 98.3 MB fp16 weights
__device__ float g_logits[BB][VV];            // 4 MB
__device__ float g_nll[BB];

__device__ __forceinline__ float sigf(float x) { return 1.f / (1.f + expf(-x)); }

__device__ __forceinline__ void cpa16(uint32_t dst, const void* src) {
  asm volatile("cp.async.cg.shared.global [%0], [%1], 16;\n" ::"r"(dst), "l"(src));
}

__device__ __forceinline__ void mma_f16(float* d, const uint32_t* a, uint32_t b0,
                                        uint32_t b1) {
  asm volatile(
      "mma.sync.aligned.m16n8k16.row.col.f32.f16.f16.f32 "
      "{%0,%1,%2,%3}, {%4,%5,%6,%7}, {%8,%9}, {%0,%1,%2,%3};\n"
      : "+f"(d[0]), "+f"(d[1]), "+f"(d[2]), "+f"(d[3])
      : "r"(a[0]), "r"(a[1]), "r"(a[2]), "r"(a[3]), "r"(b0), "r"(b1));
}

// ---------------- init ----------------
__global__ void k_init() {
  int b = blockIdx.x, h = threadIdx.x;
  g_s[b][h] = 0.f;
  g_c[b][h] = 0.f;
  if (b == 0 && h < BB) g_nll[h] = 0.f;
}

// ---------------- weight conversion: fp32 [w_b;v_b] -> fp16 pair-interleaved ----
__global__ void k_conv(const float* __restrict__ w_b, const float* __restrict__ v_b) {
  int n = blockIdx.x * 256 + threadIdx.x;
  int kp = blockIdx.y;
  int k0 = 2 * kp;
  const float* r0 = (k0 < HH) ? w_b + (size_t)k0 * VV : v_b + (size_t)(k0 - HH) * VV;
  const float* r1 =
      (k0 + 1 < HH) ? w_b + (size_t)(k0 + 1) * VV : v_b + (size_t)(k0 + 1 - HH) * VV;
  g_wh[(size_t)kp * VV + n] = __floats2half2_rn(r0[n], r1[n]);
}

// ---------------- wa_h = h_s @ w_a : [4096,1024]x[1024,512] (one-time) --------
__global__ __launch_bounds__(256) void k_wa_h(const float* __restrict__ h_s,
                                              const float* __restrict__ w_a) {
  __shared__ float As[32][64];  // [k][r]
  __shared__ float Ws[32][64];  // [k][j]
  int rb = blockIdx.x * 64;
  int jb = blockIdx.y * 64;
  int tid = threadIdx.x;
  int tx = tid & 15, ty = tid >> 4;
  float acc[4][4] = {};
  for (int k0 = 0; k0 < HH2; k0 += 32) {
    {
      int r = tid >> 2;
      int kk = (tid & 3) * 8;
      const float4* asrc =
          reinterpret_cast<const float4*>(h_s + (size_t)(rb + r) * HH2 + k0 + kk);
      float4 a0 = asrc[0], a1 = asrc[1];
      As[kk + 0][r] = a0.x; As[kk + 1][r] = a0.y; As[kk + 2][r] = a0.z; As[kk + 3][r] = a0.w;
      As[kk + 4][r] = a1.x; As[kk + 5][r] = a1.y; As[kk + 6][r] = a1.z; As[kk + 7][r] = a1.w;
    }
    {
      int kw = tid >> 3;
      int j = (tid & 7) * 8;
      const float4* wsrc =
          reinterpret_cast<const float4*>(w_a + (size_t)(k0 + kw) * HH + jb + j);
      *reinterpret_cast<float4*>(&Ws[kw][j])     = wsrc[0];
      *reinterpret_cast<float4*>(&Ws[kw][j + 4]) = wsrc[1];
    }
    __syncthreads();
#pragma unroll
    for (int k = 0; k < 32; k++) {
      float4 a = *reinterpret_cast<float4*>(&As[k][ty * 4]);
      float4 w = *reinterpret_cast<float4*>(&Ws[k][tx * 4]);
      acc[0][0] += a.x * w.x; acc[0][1] += a.x * w.y; acc[0][2] += a.x * w.z; acc[0][3] += a.x * w.w;
      acc[1][0] += a.y * w.x; acc[1][1] += a.y * w.y; acc[1][2] += a.y * w.z; acc[1][3] += a.y * w.w;
      acc[2][0] += a.z * w.x; acc[2][1] += a.z * w.y; acc[2][2] += a.z * w.z; acc[2][3] += a.z * w.w;
      acc[3][0] += a.w * w.x; acc[3][1] += a.w * w.y; acc[3][2] += a.w * w.z; acc[3][3] += a.w * w.w;
    }
    __syncthreads();
  }
#pragma unroll
  for (int ii = 0; ii < 4; ii++)
#pragma unroll
    for (int jj = 0; jj < 4; jj++)
      g_wa_h[(size_t)(rb + ty * 4 + ii) * HH + jb + tx * 4 + jj] = acc[ii][jj];
}

// ---------------- sv partials: s @ v_a, k-split (R10 known-good) ----------
__global__ __launch_bounds__(256) void k_sv(const float* __restrict__ v_a) {
  __shared__ float Ws[64][64];  // [k][j]
  __shared__ float Xs[64][33];  // [k][b]
  int jb = blockIdx.x * 64;   // 8 j-tiles
  int k0 = blockIdx.y * 64;   // 8 k-splits
  int tid = threadIdx.x;
  {
    int k = tid >> 2;
    int jq = (tid & 3) * 16;
    const float* src = v_a + (size_t)(k0 + k) * HH + jb + jq;
#pragma unroll
    for (int c = 0; c < 4; c++)
      *reinterpret_cast<float4*>(&Ws[k][jq + c * 4]) =
          *reinterpret_cast<const float4*>(src + c * 4);
  }
  {
    int b = tid >> 3;
    int k8 = (tid & 7) * 8;
    const float* src = &g_s[b][k0 + k8];
    float4 x0 = *reinterpret_cast<const float4*>(src);
    float4 x1 = *reinterpret_cast<const float4*>(src + 4);
    Xs[k8 + 0][b] = x0.x; Xs[k8 + 1][b] = x0.y; Xs[k8 + 2][b] = x0.z; Xs[k8 + 3][b] = x0.w;
    Xs[k8 + 4][b] = x1.x; Xs[k8 + 5][b] = x1.y; Xs[k8 + 6][b] = x1.z; Xs[k8 + 7][b] = x1.w;
  }
  __syncthreads();
  int tx = tid & 15, ty = tid >> 4;  // j0=tx*4, b0=ty*2
  float acc[2][4] = {};
#pragma unroll
  for (int k = 0; k < 64; k++) {
    float4 w = *reinterpret_cast<float4*>(&Ws[k][tx * 4]);
    float x0 = Xs[k][ty * 2], x1 = Xs[k][ty * 2 + 1];
    acc[0][0] += x0 * w.x; acc[0][1] += x0 * w.y; acc[0][2] += x0 * w.z; acc[0][3] += x0 * w.w;
    acc[1][0] += x1 * w.x; acc[1][1] += x1 * w.y; acc[1][2] += x1 * w.z; acc[1][3] += x1 * w.w;
  }
#pragma unroll
  for (int bi = 0; bi < 2; bi++)
#pragma unroll
    for (int ji = 0; ji < 4; ji++)
      g_svp[blockIdx.y][ty * 2 + bi][jb + tx * 4 + ji] = acc[bi][ji];
}

__global__ void k_svred() {
  int b = blockIdx.x, h = threadIdx.x;
  float s = 0.f;
#pragma unroll
  for (int ks = 0; ks < KSP; ks++) s += g_svp[ks][b][h];
  g_sv[b][h] = s;
}

// ---------------- scores[i,b] = (u_a . tanh(wa_h + sv)) * mask ----------------
__global__ __launch_bounds__(128) void k_scores(const float* __restrict__ u_a,
                                                const float* __restrict__ s_mask) {
  int i = blockIdx.x, b = blockIdx.y;
  int tid = threadIdx.x;
  const float* wah = g_wa_h + (size_t)(i * BB + b) * HH;
  float part = 0.f;
#pragma unroll
  for (int c = 0; c < 4; c++) {
    int h = tid + c * 128;
    float x = wah[h] + g_sv[b][h];
    float th;
    asm("tanh.approx.f32 %0, %1;" : "=f"(th) : "f"(x));
    part += u_a[h] * th;
  }
#pragma unroll
  for (int o = 16; o > 0; o >>= 1) part += __shfl_xor_sync(0xffffffffu, part, o);
  __shared__ float red[4];
  if ((tid & 31) == 0) red[tid >> 5] = part;
  __syncthreads();
  if (tid == 0)
    g_scores[i * BB + b] = (red[0] + red[1] + red[2] + red[3]) * s_mask[i * BB + b];
}

// ---------------- ct: inline softmax over S, then weighted sum ----------------
__global__ __launch_bounds__(128) void k_ct(const float* __restrict__ h_s, int t) {
  int b = blockIdx.x;
  int tid = threadIdx.x;  // 128 == SS
  __shared__ float al[SS];
  __shared__ float red[4];
  __shared__ float bc[2];
  float sc = g_scores[tid * BB + b];
  float m = sc;
#pragma unroll
  for (int o = 16; o > 0; o >>= 1) m = fmaxf(m, __shfl_xor_sync(0xffffffffu, m, o));
  if ((tid & 31) == 0) red[tid >> 5] = m;
  __syncthreads();
  if (tid == 0) bc[0] = fmaxf(fmaxf(red[0], red[1]), fmaxf(red[2], red[3]));
  __syncthreads();
  float e = __expf(sc - bc[0]);
  float s = e;
#pragma unroll
  for (int o = 16; o > 0; o >>= 1) s += __shfl_xor_sync(0xffffffffu, s, o);
  __syncthreads();
  if ((tid & 31) == 0) red[tid >> 5] = s;
  __syncthreads();
  if (tid == 0) bc[1] = red[0] + red[1] + red[2] + red[3];
  __syncthreads();
  al[tid] = e / bc[1];
  __syncthreads();
  int d = blockIdx.y * 128 + tid;
  float acc = 0.f;
  const float* base = h_s + (size_t)b * HH2 + d;
#pragma unroll 4
  for (int i = 0; i < SS; i++) acc += al[i] * base[(size_t)i * BB * HH2];
  g_ct[b][d] = acc;
  g_xh[t][b][HH + d] = __float2half(acc);
}

// ---------------- gates partials: [ct|s] @ [W_ih|W_hh]^T, k-split ----------------
__global__ __launch_bounds__(256) void k_gates(const float* __restrict__ W_ih,
                                               const float* __restrict__ W_hh) {
  __shared__ float Ws[64][64];  // [k][j]
  __shared__ float Xs[64][33];  // [k][b]
  int jb = blockIdx.x * 64;
  int ks = blockIdx.y;
  int tid = threadIdx.x;
  int tx = tid & 15, ty = tid >> 4;
  float acc[2][4] = {};
  for (int kt = 0; kt < 3; kt++) {
    int k0 = ks * 192 + kt * 64;
    {
      int jl = tid >> 2;
      int j = jb + jl;
      int kq = (tid & 3) * 16;
#pragma unroll
      for (int c = 0; c < 4; c++) {
        int kg = k0 + kq + c * 4;
        const float* src = (kg < HH2) ? (W_ih + (size_t)j * HH2 + kg)
                                      : (W_hh + (size_t)j * HH + (kg - HH2));
        float4 w = *reinterpret_cast<const float4*>(src);
        int kl = kq + c * 4;
        Ws[kl + 0][jl] = w.x; Ws[kl + 1][jl] = w.y; Ws[kl + 2][jl] = w.z; Ws[kl + 3][jl] = w.w;
      }
    }
    {
      int bq = tid >> 3;
      int k8 = (tid & 7) * 8;
#pragma unroll
      for (int c = 0; c < 8; c++) {
        int kg = k0 + k8 + c;
        Xs[k8 + c][bq] = (kg < HH2) ? g_ct[bq][kg] : g_s[bq][kg - HH2];
      }
    }
    __syncthreads();
#pragma unroll
    for (int k = 0; k < 64; k++) {
      float4 w = *reinterpret_cast<float4*>(&Ws[k][tx * 4]);
      float x0 = Xs[k][ty * 2], x1 = Xs[k][ty * 2 + 1];
      acc[0][0] += x0 * w.x; acc[0][1] += x0 * w.y; acc[0][2] += x0 * w.z; acc[0][3] += x0 * w.w;
      acc[1][0] += x1 * w.x; acc[1][1] += x1 * w.y; acc[1][2] += x1 * w.z; acc[1][3] += x1 * w.w;
    }
    __syncthreads();
  }
#pragma unroll
  for (int bi = 0; bi < 2; bi++)
#pragma unroll
    for (int ji = 0; ji < 4; ji++)
      g_gatesp[ks][ty * 2 + bi][jb + tx * 4 + ji] = acc[bi][ji];
}

// ---------------- LSTM cell pointwise ----------------
__global__ __launch_bounds__(512) void k_lstm(const float* __restrict__ b_ih,
                                              const float* __restrict__ b_hh, int t) {
  int b = blockIdx.x, h = threadIdx.x;
  float gi = b_ih[h] + b_hh[h];
  float gf = b_ih[HH + h] + b_hh[HH + h];
  float gg = b_ih[2 * HH + h] + b_hh[2 * HH + h];
  float go = b_ih[3 * HH + h] + b_hh[3 * HH + h];
#pragma unroll
  for (int ks = 0; ks < KSP; ks++) {
    gi += g_gatesp[ks][b][h];
    gf += g_gatesp[ks][b][HH + h];
    gg += g_gatesp[ks][b][2 * HH + h];
    go += g_gatesp[ks][b][3 * HH + h];
  }
  float c = g_c[b][h];
  float cn = sigf(gf) * c + sigf(gi) * tanhf(gg);
  float sn = sigf(go) * tanhf(cn);
  g_c[b][h] = cn;
  g_s[b][h] = sn;
  g_xh[t][b][h] = __float2half(sn);
}

// ---------------- logits via fp16 mma (R7 config) ----------------
__global__ __launch_bounds__(LTH, 1) void k_logits_mma(int t) {
  extern __shared__ uint32_t smw[];
  const int nb = blockIdx.x * LN;
  const int tid = threadIdx.x;
  const int warp = tid >> 5, lane = tid & 31;
  const int grp = lane >> 2, tig = lane & 3;

  uint32_t sbase = (uint32_t)__cvta_generic_to_shared(smw);
  const uint32_t xbase = sbase + NSTG * WBUF * 4;

  const int wr0 = tid >> 6;
  const int wn4 = (tid & 63) * 4;
  const int xrow = tid >> 2;
  const int xo = tid & 3;

  float acc[2][4][4];
#pragma unroll
  for (int i = 0; i < 2; i++)
#pragma unroll
    for (int j = 0; j < 4; j++)
#pragma unroll
      for (int k = 0; k < 4; k++) acc[i][j][k] = 0.f;

#define STAGE(buf, kp0)                                                            \
  do {                                                                             \
    _Pragma("unroll") for (int kk = 0; kk < 4; kk++) {                             \
      int r = wr0 + kk * 4;                                                        \
      cpa16(sbase + ((buf)*WBUF + r * WST + wn4) * 4,                              \
            g_wh + (size_t)((kp0) + r) * VV + nb + wn4);                           \
    }                                                                              \
    if (tid < 128)                                                                 \
      cpa16(xbase + ((buf)*XBUF + xrow * XST + xo * 4) * 4,                        \
            &g_xh[t][xrow][(kp0)*2 + xo * 8]);                                     \
  } while (0)

#pragma unroll
  for (int p = 0; p < NSTG - 1; p++) {
    STAGE(p, p * KP);
    asm volatile("cp.async.commit_group;\n");
  }

  for (int c = 0; c < NCH; c++) {
    int buf = c & (NSTG - 1);
    asm volatile("cp.async.wait_group %0;\n" ::"n"(NSTG - 2));
    __syncthreads();

    if (c + NSTG - 1 < NCH) STAGE((c + NSTG - 1) & (NSTG - 1), (c + NSTG - 1) * KP);
    asm volatile("cp.async.commit_group;\n");

    const uint32_t* Wc = smw + buf * WBUF;
    const uint32_t* Xc = smw + NSTG * WBUF + buf * XBUF;
#pragma unroll
    for (int ks2 = 0; ks2 < KP; ks2 += 8) {
      uint32_t A[2][4];
#pragma unroll
      for (int mt = 0; mt < 2; mt++) {
        int r0 = mt * 16 + grp;
        A[mt][0] = Xc[r0 * XST + ks2 + tig];
        A[mt][1] = Xc[(r0 + 8) * XST + ks2 + tig];
        A[mt][2] = Xc[r0 * XST + ks2 + 4 + tig];
        A[mt][3] = Xc[(r0 + 8) * XST + ks2 + 4 + tig];
      }
#pragma unroll
      for (int nt = 0; nt < 4; nt++) {
        int n0 = warp * 32 + nt * 8 + grp;
        uint32_t B0 = Wc[(ks2 + tig) * WST + n0];
        uint32_t B1 = Wc[(ks2 + 4 + tig) * WST + n0];
        mma_f16(acc[0][nt], A[0], B0, B1);
        mma_f16(acc[1][nt], A[1], B0, B1);
      }
    }
  }
#undef STAGE

#pragma unroll
  for (int mt = 0; mt < 2; mt++) {
#pragma unroll
    for (int nt = 0; nt < 4; nt++) {
      int row = mt * 16 + grp;
      int col = nb + warp * 32 + nt * 8 + tig * 2;
      float2 lo = {acc[mt][nt][0], acc[mt][nt][1]};
      float2 hi = {acc[mt][nt][2], acc[mt][nt][3]};
      *reinterpret_cast<float2*>(&g_logits[row][col]) = lo;
      *reinterpret_cast<float2*>(&g_logits[row + 8][col]) = hi;
    }
  }
}

// ---------------- softmax over V, write p_gen, accumulate NLL ----------------
__global__ __launch_bounds__(512) void k_softmax(float* __restrict__ out,
                                                 const int* __restrict__ t_indices,
                                                 const float* __restrict__ t_mask,
                                                 int t, long long p_off) {
  int b = blockIdx.x, tid = threadIdx.x;
  const float* lg = g_logits[b];
  __shared__ float red[16];
  __shared__ float bc[2];
  float m = -3.4e38f;
  for (int v = tid; v < VV; v += 512) m = fmaxf(m, lg[v]);
#pragma unroll
  for (int o = 16; o > 0; o >>= 1) m = fmaxf(m, __shfl_xor_sync(0xffffffffu, m, o));
  if ((tid & 31) == 0) red[tid >> 5] = m;
  __syncthreads();
  if (tid == 0) {
    float mm = red[0];
#pragma unroll
    for (int w = 1; w < 16; w++) mm = fmaxf(mm, red[w]);
    bc[0] = mm;
  }
  __syncthreads();
  m = bc[0];
  float s = 0.f;
  for (int v = tid; v < VV; v += 512) s += __expf(lg[v] - m);
#pragma unroll
  for (int o = 16; o > 0; o >>= 1) s += __shfl_xor_sync(0xffffffffu, s, o);
  __syncthreads();
  if ((tid & 31) == 0) red[tid >> 5] = s;
  __syncthreads();
  if (tid == 0) {
    float ss = 0.f;
#pragma unroll
    for (int w = 0; w < 16; w++) ss += red[w];
    bc[1] = ss;
  }
  __syncthreads();
  float Z = bc[1];
  float inv = 1.f / Z;
  float* dst = out + p_off + ((long long)t * BB + b) * VV;
  for (int v = tid; v < VV; v += 512) dst[v] = __expf(lg[v] - m) * inv;
  if (tid == 0) {
    int idx = t_indices[t * BB + b];
    g_nll[b] += -(lg[idx] - m - logf(Z)) * t_mask[t * BB + b];
  }
}

// ---------------- final loss ----------------
__global__ void k_loss(float* __restrict__ out, const float* __restrict__ t_mask) {
  int b = threadIdx.x;  // 32
  float s = 0.f;
  for (int t = 0; t < TT; t++) s += t_mask[t * BB + b];
  out[b] = g_nll[b] / s;
}

// ---------------- launch: dual-stream pipelined graph (no evBL hazard) -------
extern "C" void kernel_launch(void* const* d_in, const int* in_sizes, int n_in,
                              void* d_out, int out_size) {
  const float* h_s    = (const float*)d_in[0];
  const float* s_mask = (const float*)d_in[1];
  const float* w_a    = (const float*)d_in[2];
  const float* v_a    = (const float*)d_in[3];
  const float* u_a    = (const float*)d_in[4];
  const float* w_b    = (const float*)d_in[5];
  const float* v_b    = (const float*)d_in[6];
  const float* W_ih   = (const float*)d_in[7];
  const float* W_hh   = (const float*)d_in[8];
  const float* b_ih   = (const float*)d_in[9];
  const float* b_hh   = (const float*)d_in[10];
  const float* t_mask = (const float*)d_in[11];
  const int*   t_idx  = (const int*)d_in[12];
  float* out = (float*)d_out;

  long long p_off = (long long)out_size - (long long)TT * BB * VV;
  if (p_off < 0) p_off = 0;

  static cudaStream_t sA = nullptr, sB = nullptr;
  static cudaEvent_t evFork, evA[TT], evLastA, evLastB;
  if (sA == nullptr) {
    cudaStreamCreateWithFlags(&sA, cudaStreamNonBlocking);
    cudaStreamCreateWithFlags(&sB, cudaStreamNonBlocking);
    cudaEventCreateWithFlags(&evFork, cudaEventDisableTiming);
    cudaEventCreateWithFlags(&evLastA, cudaEventDisableTiming);
    cudaEventCreateWithFlags(&evLastB, cudaEventDisableTiming);
    for (int t = 0; t < TT; t++)
      cudaEventCreateWithFlags(&evA[t], cudaEventDisableTiming);
    cudaFuncSetAttribute(k_logits_mma, cudaFuncAttributeMaxDynamicSharedMemorySize,
                         LSMEM_BYTES);
  }

  // prologue on origin (default) stream
  k_init<<<BB, HH>>>();
  k_conv<<<dim3(VV / 256, KK / 2), 256>>>(w_b, v_b);
  k_wa_h<<<dim3(64, 8), 256>>>(h_s, w_a);

  // fork capture into sA (recurrence) and sB (output head)
  cudaEventRecord(evFork, 0);
  cudaStreamWaitEvent(sA, evFork, 0);
  cudaStreamWaitEvent(sB, evFork, 0);

  for (int t = 0; t < TT; t++) {
    k_sv<<<dim3(8, KSP), 256, 0, sA>>>(v_a);
    k_svred<<<BB, HH, 0, sA>>>();
    k_scores<<<dim3(SS, BB), 128, 0, sA>>>(u_a, s_mask);
    k_ct<<<dim3(BB, 8), 128, 0, sA>>>(h_s, t);
    k_gates<<<dim3(32, KSP), 256, 0, sA>>>(W_ih, W_hh);
    k_lstm<<<BB, HH, 0, sA>>>(b_ih, b_hh, t);
    cudaEventRecord(evA[t], sA);

    cudaStreamWaitEvent(sB, evA[t], 0);
    k_logits_mma<<<VV / LN, LTH, LSMEM_BYTES, sB>>>(t);
    k_softmax<<<BB, 512, 0, sB>>>(out, t_idx, t_mask, t, p_off);
  }

  // join both branches back into origin stream before k_loss
  cudaEventRecord(evLastA, sA);
  cudaEventRecord(evLastB, sB);
  cudaStreamWaitEvent((cudaStream_t)0, evLastA, 0);
  cudaStreamWaitEvent((cudaStream_t)0, evLastB, 0);
  k_loss<<<1, BB>>>(out, t_mask);
}